// round 1
// baseline (speedup 1.0000x reference)
#include <cuda_runtime.h>
#include <math.h>

#define NWIRES 9
#define NLAYERS 4
#define DDIM 512
#define BATCH 64
#define PPAR 72
#define NGATES 36
#define EMBED 512

// Scratch (allocation-free: __device__ globals)
__device__ float g_params[BATCH * PPAR];
__device__ float g_coef[BATCH * NGATES * 4];   // c, s, cphi, sphi per gate
__device__ float g_scal[BATCH * 4];            // a1=sin(th)/th, a2=(1-cos th)/th^2, cos th
__device__ float g_Uv[BATCH * DDIM];

// ---------------------------------------------------------------------------
// K1: MLP -> params, gate trig coefficients, rank-2 scalars, zero Uv
// ---------------------------------------------------------------------------
__global__ void k1_params(const float* __restrict__ t, const float* __restrict__ w1,
                          const float* __restrict__ b1, const float* __restrict__ w2,
                          const float* __restrict__ b2) {
    int b = blockIdx.x;
    int tid = threadIdx.x; // 128 threads
    __shared__ float h[EMBED];
    __shared__ float p[PPAR];

    float tv = t[b];
    for (int e = tid; e < EMBED; e += 128) {
        float x = fmaf(tv, w1[e], b1[e]);
        h[e] = x / (1.f + expf(-x));   // silu
    }
    __syncthreads();

    if (tid < PPAR) {
        float acc = b2[tid];
        for (int e = 0; e < EMBED; e++) acc = fmaf(h[e], w2[e * PPAR + tid], acc);
        p[tid] = acc;
        g_params[b * PPAR + tid] = acc;
    }
    __syncthreads();

    if (tid < NGATES) {
        float thy = p[2 * tid], thz = p[2 * tid + 1];
        float* dst = &g_coef[(b * NGATES + tid) * 4];
        dst[0] = cosf(0.5f * thy);
        dst[1] = sinf(0.5f * thy);
        dst[2] = cosf(0.5f * thz);
        dst[3] = sinf(0.5f * thz);
    }
    for (int i = tid; i < DDIM; i += 128) g_Uv[b * DDIM + i] = 0.f;

    if (tid == 0) {
        float s2 = 0.f;
        for (int j = 1; j < PPAR; j++) { float vj = 0.01f * p[j]; s2 = fmaf(vj, vj, s2); }
        float th = sqrtf(s2);
        float ct = cosf(th);
        float a1, a2;
        if (th > 1e-6f) { a1 = sinf(th) / th; a2 = (1.f - ct) / s2; }
        else            { a1 = 1.f - s2 * (1.f / 6.f); a2 = 0.5f; }
        g_scal[b * 4 + 0] = a1;
        g_scal[b * 4 + 1] = a2;
        g_scal[b * 4 + 2] = ct;
    }
}

// ---------------------------------------------------------------------------
// K2: circuit simulation. One column (initial basis state) per warp.
// Amp index n (9 bits): lane = bits[8:4], register slot r = bits[3:0].
// Wire w acts on bit position p = 8 - w (wire 0 = MSB per reference reshape).
// Ring of CNOTs per layer composed into one permutation:
//   pi(n): b0'=b0^b1 ... b6'=b6^b7, b7'=b7^b8^b0, b8'=b8^b0; new[n]=old[pi(n)]
// ---------------------------------------------------------------------------
__global__ __launch_bounds__(512) void k2_sim(float* __restrict__ out) {
    int b    = blockIdx.x >> 5;   // batch
    int grp  = blockIdx.x & 31;   // 32 groups x 16 columns
    int wid  = threadIdx.x >> 5;
    int lane = threadIdx.x & 31;
    int col  = grp * 16 + wid;

    __shared__ float4 gc[NGATES];
    __shared__ float tile[16][513];

    if (threadIdx.x < NGATES) {
        const float* src = &g_coef[(b * NGATES + threadIdx.x) * 4];
        gc[threadIdx.x] = make_float4(src[0], src[1], src[2], src[3]);
    }
    __syncthreads();

    float re[16], im[16];
#pragma unroll
    for (int r = 0; r < 16; r++) {
        re[r] = (((lane << 4) | r) == col) ? 1.f : 0.f;
        im[r] = 0.f;
    }

    const int par = __popc(lane) & 1;
    const int gl  = lane ^ (lane >> 1);

#pragma unroll 1
    for (int L = 0; L < NLAYERS; L++) {
#pragma unroll
        for (int w = 0; w < NWIRES; w++) {
            float4 g4 = gc[L * NWIRES + w];
            float c = g4.x, s = g4.y, cp = g4.z, sp = g4.w;
            const int pbit = 8 - w;
            if (pbit >= 4) {
                // lane-bit gate: pair across lanes via shfl_xor
                const int q = pbit - 4;
                int bv = (lane >> q) & 1;
                float ss  = bv ? s  : -s;
                float sps = bv ? sp : -sp;
#pragma unroll
                for (int r = 0; r < 16; r++) {
                    float ore = __shfl_xor_sync(0xffffffffu, re[r], 1 << q);
                    float oim = __shfl_xor_sync(0xffffffffu, im[r], 1 << q);
                    float tre = fmaf(c, re[r], ss * ore);
                    float tim = fmaf(c, im[r], ss * oim);
                    re[r] = fmaf(cp, tre, -sps * tim);
                    im[r] = fmaf(cp, tim,  sps * tre);
                }
            } else {
                // register-bit gate: pairs within the 16 slots
                const int bit = 1 << pbit;
#pragma unroll
                for (int r0 = 0; r0 < 16; r0++) {
                    if (r0 & bit) continue;
                    const int r1 = r0 | bit;
                    float t0r = fmaf(c, re[r0], -s * re[r1]);
                    float t0i = fmaf(c, im[r0], -s * im[r1]);
                    float t1r = fmaf(s, re[r0],  c * re[r1]);
                    float t1i = fmaf(s, im[r0],  c * im[r1]);
                    re[r0] = fmaf(cp, t0r,  sp * t0i);   // * e^{-i phi}
                    im[r0] = fmaf(cp, t0i, -sp * t0r);
                    re[r1] = fmaf(cp, t1r, -sp * t1i);   // * e^{+i phi}
                    im[r1] = fmaf(cp, t1i,  sp * t1r);
                }
            }
        }
        // composed CNOT-ring permutation: new[l,r] = old[srcLane, srcR]
        // srcLane = gray(l) (^24 if r odd); source lane presents slot
        // (r^(r>>1)) ^ (parity(srcLane)<<3)
        float nre[16], nim[16];
#pragma unroll
        for (int r = 0; r < 16; r++) {
            const int idx = r ^ (r >> 1);
            int src = (r & 1) ? (gl ^ 24) : gl;
            float pre = par ? re[idx ^ 8] : re[idx];
            float pim = par ? im[idx ^ 8] : im[idx];
            nre[r] = __shfl_sync(0xffffffffu, pre, src);
            nim[r] = __shfl_sync(0xffffffffu, pim, src);
        }
#pragma unroll
        for (int r = 0; r < 16; r++) { re[r] = nre[r]; im[r] = nim[r]; }
    }

    // stage real part into smem for coalesced writeback
#pragma unroll
    for (int r = 0; r < 16; r++) tile[wid][(lane << 4) | r] = re[r];

    // Uv[b][i] += Re(U[i,col]) * v[col] for col in 1..71
    if (col >= 1 && col < PPAR) {
        float vc = 0.01f * g_params[b * PPAR + col];
        float* uv = &g_Uv[b * DDIM];
#pragma unroll
        for (int r = 0; r < 16; r++)
            atomicAdd(&uv[(lane << 4) | r], re[r] * vc);
    }

    __syncthreads();

    // coalesced write: out[b][j][grp*16 + c]
    float* obase = out + (size_t)b * DDIM * DDIM + grp * 16;
    int c  = threadIdx.x & 15;
    int j0 = threadIdx.x >> 4;   // 0..31
#pragma unroll
    for (int k = 0; k < 16; k++) {
        int j = k * 32 + j0;
        obase[(size_t)j * DDIM + c] = tile[c][j];
    }
}

// ---------------------------------------------------------------------------
// K3: rank-2 expm update, touches only columns 0..71. One warp per row.
// C[i,j] += (a1*u0 - a2*Uv_i) * v[j]          (j = 1..71)
// C[i,0]  = cos(th)*u0 - a1*Uv_i
// ---------------------------------------------------------------------------
__global__ void k3_update(float* __restrict__ out) {
    int gw   = (blockIdx.x * blockDim.x + threadIdx.x) >> 5;
    int lane = threadIdx.x & 31;
    int b = gw >> 9;
    int i = gw & 511;
    if (b >= BATCH) return;

    float* row = out + ((size_t)b * DDIM + i) * DDIM;
    float u0  = row[0];
    float uvi = g_Uv[b * DDIM + i];
    float a1 = g_scal[b * 4 + 0];
    float a2 = g_scal[b * 4 + 1];
    float ct = g_scal[b * 4 + 2];
    float f = fmaf(a1, u0, -a2 * uvi);

#pragma unroll
    for (int jj = 0; jj < 3; jj++) {
        int j = lane + jj * 32;
        if (j >= PPAR) break;
        float val;
        if (j == 0) val = fmaf(u0, ct, -a1 * uvi);
        else        val = fmaf(f, 0.01f * g_params[b * PPAR + j], row[j]);
        row[j] = val;
    }
}

// ---------------------------------------------------------------------------
extern "C" void kernel_launch(void* const* d_in, const int* in_sizes, int n_in,
                              void* d_out, int out_size) {
    const float* t  = (const float*)d_in[0];
    const float* w1 = (const float*)d_in[1];
    const float* b1 = (const float*)d_in[2];
    const float* w2 = (const float*)d_in[3];
    const float* b2 = (const float*)d_in[4];
    float* out = (float*)d_out;

    k1_params<<<BATCH, 128>>>(t, w1, b1, w2, b2);
    k2_sim<<<BATCH * 32, 512>>>(out);
    k3_update<<<(BATCH * DDIM) / 8, 256>>>(out);
}